// round 4
// baseline (speedup 1.0000x reference)
#include <cuda_runtime.h>
#include <cuda_bf16.h>
#include <stdint.h>

typedef __nv_bfloat16 bf16;

// ---------------- static device scratch (no runtime allocation) -------------
__device__ bf16 d_embB[(size_t)50000 * 304];   // padded bf16 embedding [v][304]
__device__ bf16 d_WxT[(size_t)2048 * 304];     // Wx transposed [n][304] bf16
__device__ bf16 d_WhB[512 * 2048];
__device__ bf16 d_W1B[512 * 1024];
__device__ bf16 d_W2B[1024 * 1024];
__device__ bf16 d_xg[(size_t)32768 * 2048];    // time-major [t][b][g]
__device__ bf16 d_h[2][64 * 512];              // ping-pong h
__device__ unsigned char d_maskT[512 * 64];    // [t][b]
__device__ bf16 d_a1[64 * 1024];
__device__ bf16 d_a2[64 * 1024];
__device__ unsigned int d_flags[512];          // per-CTA barrier flags, 32B-padded

// ---------------- helpers ---------------------------------------------------
__device__ __forceinline__ uint32_t pack_bf2(float a, float b) {
    __nv_bfloat162 t = __floats2bfloat162_rn(a, b);
    return *reinterpret_cast<uint32_t*>(&t);
}

__device__ __forceinline__ void mma16816(float* c, const uint32_t* a, const uint32_t* b) {
    asm volatile(
        "mma.sync.aligned.m16n8k16.row.col.f32.bf16.bf16.f32 "
        "{%0,%1,%2,%3},{%4,%5,%6,%7},{%8,%9},{%0,%1,%2,%3};"
        : "+f"(c[0]), "+f"(c[1]), "+f"(c[2]), "+f"(c[3])
        : "r"(a[0]), "r"(a[1]), "r"(a[2]), "r"(a[3]), "r"(b[0]), "r"(b[1]));
}

__device__ __forceinline__ void ldsm4(uint32_t* r, uint32_t addr) {
    asm volatile("ldmatrix.sync.aligned.m8n8.x4.shared.b16 {%0,%1,%2,%3}, [%4];"
                 : "=r"(r[0]), "=r"(r[1]), "=r"(r[2]), "=r"(r[3]) : "r"(addr));
}

__device__ __forceinline__ uint32_t s2u(const void* p) {
    return (uint32_t)__cvta_generic_to_shared(p);
}

__device__ __forceinline__ void cp16(uint32_t dst, const void* src) {
    asm volatile("cp.async.cg.shared.global [%0], [%1], 16;" :: "r"(dst), "l"(src));
}

__device__ __forceinline__ void cp_wait_all() {
    asm volatile("cp.async.commit_group;\ncp.async.wait_group 0;" ::: "memory");
}

__device__ __forceinline__ void st_release(unsigned int* p, unsigned int v) {
    asm volatile("st.global.release.gpu.b32 [%0], %1;" :: "l"(p), "r"(v) : "memory");
}

__device__ __forceinline__ unsigned int ld_acquire(const unsigned int* p) {
    unsigned int v;
    asm volatile("ld.global.acquire.gpu.b32 %0, [%1];" : "=r"(v) : "l"(p) : "memory");
    return v;
}

// ---------------- launch 0: vectorized embedding conversion ------------------
// 50000 rows x 38 uint4-chunks; j==37 pads cols 300..303 with zero.
__global__ void k_cvt_emb(const float* __restrict__ e) {
    int i = blockIdx.x * 256 + threadIdx.x;
    if (i >= 50000 * 38) return;
    int row = i / 38, j = i - 38 * row;
    const float* src = e + (size_t)row * 300 + j * 8;
    float4 lo = *reinterpret_cast<const float4*>(src);
    float4 hi = make_float4(0.f, 0.f, 0.f, 0.f);
    if (j < 37) hi = *reinterpret_cast<const float4*>(src + 4);
    uint4 o;
    o.x = pack_bf2(lo.x, lo.y); o.y = pack_bf2(lo.z, lo.w);
    o.z = pack_bf2(hi.x, hi.y); o.w = pack_bf2(hi.z, hi.w);
    *reinterpret_cast<uint4*>(&d_embB[(size_t)row * 304 + j * 8]) = o;
}

// ---------------- launch 1: everything else (WxT, Wh/W1/W2, mask, zero) -----
__global__ void k_cvt_rest(const float* __restrict__ Wx, const float* __restrict__ Wh,
                           const float* __restrict__ W1, const float* __restrict__ W2,
                           const int* __restrict__ tokens) {
    int i = blockIdx.x * 256 + threadIdx.x;
    if (i < 622592) {                       // WxT (transpose, scalar)
        int n = i / 304, k = i - 304 * n;
        d_WxT[i] = __float2bfloat16(k < 300 ? Wx[(size_t)k * 2048 + n] : 0.f);
    } else if (i < 950272) {                // Wh/W1/W2, 8 elements per thread
        int j = i - 622592;
        const float* src; bf16* dst;
        if (j < 131072)      { src = Wh + (size_t)j * 8;            dst = d_WhB + (size_t)j * 8; }
        else if (j < 196608) { src = W1 + (size_t)(j - 131072) * 8; dst = d_W1B + (size_t)(j - 131072) * 8; }
        else                 { src = W2 + (size_t)(j - 196608) * 8; dst = d_W2B + (size_t)(j - 196608) * 8; }
        float4 lo = *reinterpret_cast<const float4*>(src);
        float4 hi = *reinterpret_cast<const float4*>(src + 4);
        uint4 o;
        o.x = pack_bf2(lo.x, lo.y); o.y = pack_bf2(lo.z, lo.w);
        o.z = pack_bf2(hi.x, hi.y); o.w = pack_bf2(hi.z, hi.w);
        *reinterpret_cast<uint4*>(dst) = o;
    } else if (i < 983040) {                // transposed mask
        int j = i - 950272;
        int t = j >> 6, b = j & 63;
        d_maskT[j] = (tokens[b * 512 + t] != 0) ? 1 : 0;
    } else if (i < 987136) {                // zero h[0] (uint4)
        uint4 z = make_uint4(0u, 0u, 0u, 0u);
        reinterpret_cast<uint4*>(d_h[0])[i - 983040] = z;
    } else if (i < 987648) {                // zero flags
        d_flags[i - 987136] = 0u;
    }
}

// ---------------- launch 2: Phase A  xg = gather(emb)@Wx + b ----------------
__global__ void __launch_bounds__(256) k_phaseA(const int* __restrict__ tokens,
                                                const float* __restrict__ bias) {
    extern __shared__ bf16 smA[];
    bf16* As = smA;                 // 128 x 312
    bf16* Bs = smA + 128 * 312;     // 128 x 312
    __shared__ int stok[128];

    int tid = threadIdx.x;
    int n0 = blockIdx.x * 128;
    int m0 = blockIdx.y * 128;
    if (tid < 128) stok[tid] = tokens[m0 + tid];
    __syncthreads();

    // cp.async load: 2 threads per row, 19 x 16B each for A and B
    {
        int row = tid >> 1, half = tid & 1;
        const bf16* sa = &d_embB[(size_t)stok[row] * 304 + half * 152];
        uint32_t da = s2u(&As[row * 312 + half * 152]);
        const bf16* sb = &d_WxT[(size_t)(n0 + row) * 304 + half * 152];
        uint32_t db = s2u(&Bs[row * 312 + half * 152]);
        #pragma unroll
        for (int j = 0; j < 19; j++) {
            cp16(da + j * 16, sa + j * 8);
            cp16(db + j * 16, sb + j * 8);
        }
        cp_wait_all();
    }
    __syncthreads();

    int w = tid >> 5, lane = tid & 31, g = lane >> 2, tq = lane & 3;
    int wm = (w >> 2) * 64;
    int wn = (w & 3) * 32;
    int lr = lane & 7, lm = lane >> 3;

    uint32_t aab[4], bab[2];
    #pragma unroll
    for (int mo = 0; mo < 4; mo++)
        aab[mo] = s2u(&As[(wm + mo * 16 + lr + (lm & 1) * 8) * 312 + (lm >> 1) * 8]);
    bab[0] = s2u(&Bs[(wn +      lr + (lm >> 1) * 8) * 312 + (lm & 1) * 8]);
    bab[1] = s2u(&Bs[(wn + 16 + lr + (lm >> 1) * 8) * 312 + (lm & 1) * 8]);

    float C[4][4][4];
    #pragma unroll
    for (int a = 0; a < 4; a++)
        #pragma unroll
        for (int b2 = 0; b2 < 4; b2++)
            #pragma unroll
            for (int c = 0; c < 4; c++) C[a][b2][c] = 0.f;

    #pragma unroll 1
    for (int ks = 0; ks < 19; ks++) {
        uint32_t B8[8];
        ldsm4(B8, bab[0] + ks * 32);
        ldsm4(B8 + 4, bab[1] + ks * 32);
        #pragma unroll
        for (int mo = 0; mo < 4; mo++) {
            uint32_t A4[4];
            ldsm4(A4, aab[mo] + ks * 32);
            mma16816(C[mo][0], A4, B8 + 0);
            mma16816(C[mo][1], A4, B8 + 2);
            mma16816(C[mo][2], A4, B8 + 4);
            mma16816(C[mo][3], A4, B8 + 6);
        }
    }

    #pragma unroll
    for (int mo = 0; mo < 4; mo++) {
        #pragma unroll
        for (int no = 0; no < 4; no++) {
            int gcol = n0 + wn + no * 8 + 2 * tq;
            float b0 = bias[gcol], b1v = bias[gcol + 1];
            int m1 = m0 + wm + mo * 16 + g;
            int m2 = m1 + 8;
            size_t o1 = ((size_t)((m1 & 511) * 64 + (m1 >> 9))) * 2048 + gcol;
            size_t o2 = ((size_t)((m2 & 511) * 64 + (m2 >> 9))) * 2048 + gcol;
            *reinterpret_cast<uint32_t*>(&d_xg[o1]) =
                pack_bf2(C[mo][no][0] + b0, C[mo][no][1] + b1v);
            *reinterpret_cast<uint32_t*>(&d_xg[o2]) =
                pack_bf2(C[mo][no][2] + b0, C[mo][no][3] + b1v);
        }
    }
}

// ---------------- launch 3 (profiled): recurrence ----------------------------
// 64 persistent CTAs x 8 units, 512 steps.
// dyn SMEM: Ws 32x520 (33280 B) | hs 64x520 (66560 B) | gb 64x36 (4608 B) |
//           ms 64 B  -> total 104512 B
__global__ void __launch_bounds__(256, 1) k_recur() {
    extern __shared__ char smraw[];
    bf16* Ws = reinterpret_cast<bf16*>(smraw);
    bf16* hs = reinterpret_cast<bf16*>(smraw + 33280);
    bf16* gb = reinterpret_cast<bf16*>(smraw + 99840);
    uint32_t* ms4 = reinterpret_cast<uint32_t*>(smraw + 104448);

    int tid = threadIdx.x, cta = blockIdx.x;
    int u0 = cta * 8;

    for (int i = tid; i < 32 * 512; i += 256) {
        int n = i & 31, k = i >> 5;
        int gcol = (n >> 3) * 512 + u0 + (n & 7);
        Ws[n * 520 + k] = d_WhB[k * 2048 + gcol];
    }

    int w = tid >> 5, lane = tid & 31, g = lane >> 2, tq = lane & 3;
    int wm = (w & 3) * 16;
    int wn = (w >> 2) * 16;
    int lr = lane & 7, lm = lane >> 3;
    uint32_t a_base = s2u(&hs[(wm + lr + (lm & 1) * 8) * 520 + (lm >> 1) * 8]);
    uint32_t b_base = s2u(&Ws[(wn + lr + (lm >> 1) * 8) * 520 + (lm & 1) * 8]);

    int uu = tid & 7, er = tid >> 3;
    float cst[2] = {0.f, 0.f};
    __syncthreads();

    for (int t = 0; t < 512; t++) {
        const bf16* hsrc = d_h[t & 1];
        for (int i = tid; i < 4096; i += 256) {
            int row = i >> 6, qc = i & 63;
            *reinterpret_cast<uint4*>(&hs[row * 520 + qc * 8]) =
                __ldcg(reinterpret_cast<const uint4*>(&hsrc[row * 512 + qc * 8]));
        }
        if (tid < 16)
            ms4[tid] = *reinterpret_cast<const uint32_t*>(&d_maskT[t * 64 + tid * 4]);
        __syncthreads();

        // prefetch xg gate values (DRAM) so they overlap the MMA loop
        const bf16* xg = d_xg + (size_t)t * 131072;
        bf16 xv[8];
        {
            const bf16* xr0 = xg + er * 2048 + u0 + uu;
            const bf16* xr1 = xg + (er + 32) * 2048 + u0 + uu;
            xv[0] = xr0[0]; xv[1] = xr0[512]; xv[2] = xr0[1024]; xv[3] = xr0[1536];
            xv[4] = xr1[0]; xv[5] = xr1[512]; xv[6] = xr1[1024]; xv[7] = xr1[1536];
        }

        float C0[4] = {0.f, 0.f, 0.f, 0.f};
        float C1[4] = {0.f, 0.f, 0.f, 0.f};
        #pragma unroll 8
        for (int ks = 0; ks < 32; ks++) {
            uint32_t A4[4], B4[4];
            ldsm4(A4, a_base + ks * 32);
            ldsm4(B4, b_base + ks * 32);
            mma16816(C0, A4, B4);
            mma16816(C1, A4, B4 + 2);
        }
        {
            int col0 = wn + 2 * tq;
            *reinterpret_cast<uint32_t*>(&gb[(wm + g) * 36 + col0])         = pack_bf2(C0[0], C0[1]);
            *reinterpret_cast<uint32_t*>(&gb[(wm + g + 8) * 36 + col0])     = pack_bf2(C0[2], C0[3]);
            *reinterpret_cast<uint32_t*>(&gb[(wm + g) * 36 + col0 + 8])     = pack_bf2(C1[0], C1[1]);
            *reinterpret_cast<uint32_t*>(&gb[(wm + g + 8) * 36 + col0 + 8]) = pack_bf2(C1[2], C1[3]);
        }
        __syncthreads();

        bf16* hdst = d_h[(t + 1) & 1];
        #pragma unroll
        for (int it = 0; it < 2; it++) {
            int r = er + it * 32;
            float gi = __bfloat162float(gb[r * 36 + uu])      + __bfloat162float(xv[it * 4 + 0]);
            float gf = __bfloat162float(gb[r * 36 + 8 + uu])  + __bfloat162float(xv[it * 4 + 1]);
            float gc = __bfloat162float(gb[r * 36 + 16 + uu]) + __bfloat162float(xv[it * 4 + 2]);
            float go = __bfloat162float(gb[r * 36 + 24 + uu]) + __bfloat162float(xv[it * 4 + 3]);
            float si = 1.f / (1.f + __expf(-gi));
            float sf = 1.f / (1.f + __expf(-gf));
            float so = 1.f / (1.f + __expf(-go));
            float cn = sf * cst[it] + si * fmaxf(gc, 0.f);
            float hn = so * fmaxf(cn, 0.f);
            float hout;
            if ((ms4[r >> 2] >> ((r & 3) * 8)) & 0xff) { cst[it] = cn; hout = hn; }
            else { hout = __bfloat162float(hs[r * 520 + u0 + uu]); }
            hdst[r * 512 + u0 + uu] = __float2bfloat16(hout);
        }
        __syncthreads();   // all h stores issued

        if (t < 511) {
            // distributed release/acquire barrier: no atomics, parallel polling
            if (tid == 0) st_release(&d_flags[cta * 8], (unsigned)(t + 1));
            if (tid < 64) {
                while (ld_acquire(&d_flags[tid * 8]) < (unsigned)(t + 1)) { }
            }
            __syncthreads();
        }
    }
}

// ---------------- MLP layers -------------------------------------------------
__global__ void __launch_bounds__(256) k_mlp(int mode, const float* __restrict__ bias) {
    const bf16* A; const bf16* W; bf16* out; int K;
    if (mode == 0) { A = d_h[0]; W = d_W1B; out = d_a1; K = 512; }
    else           { A = d_a1;   W = d_W2B; out = d_a2; K = 1024; }
    int tid = threadIdx.x;
    int col = blockIdx.x * 64 + (tid & 63);
    int rb = blockIdx.y * 16 + (tid >> 6);
    float acc[4] = {0.f, 0.f, 0.f, 0.f};
    for (int k = 0; k < K; k++) {
        float wv = __bfloat162float(W[k * 1024 + col]);
        #pragma unroll
        for (int j = 0; j < 4; j++)
            acc[j] += __bfloat162float(A[(rb + 4 * j) * K + k]) * wv;
    }
    float bv = bias[col];
    #pragma unroll
    for (int j = 0; j < 4; j++)
        out[(rb + 4 * j) * 1024 + col] = __float2bfloat16(fmaxf(acc[j] + bv, 0.f));
}

// ---------------- logits + softmax ------------------------------------------
__global__ void __launch_bounds__(128) k_out(const float* __restrict__ Wo,
                                             const float* __restrict__ bo,
                                             float* __restrict__ out) {
    __shared__ float red[128 * 20];
    int row = blockIdx.x, tid = threadIdx.x;
    float p[20];
    #pragma unroll
    for (int c = 0; c < 20; c++) p[c] = 0.f;
    for (int k = tid; k < 1024; k += 128) {
        float a = __bfloat162float(d_a2[row * 1024 + k]);
        #pragma unroll
        for (int c = 0; c < 20; c++) p[c] += a * Wo[k * 20 + c];
    }
    #pragma unroll
    for (int c = 0; c < 20; c++) red[tid * 20 + c] = p[c];
    __syncthreads();
    for (int s = 64; s > 0; s >>= 1) {
        if (tid < s) {
            #pragma unroll
            for (int c = 0; c < 20; c++) red[tid * 20 + c] += red[(tid + s) * 20 + c];
        }
        __syncthreads();
    }
    if (tid == 0) {
        float l[20], mx = -1e30f, ss = 0.f;
        #pragma unroll
        for (int c = 0; c < 20; c++) { l[c] = red[c] + bo[c]; mx = fmaxf(mx, l[c]); }
        #pragma unroll
        for (int c = 0; c < 20; c++) { l[c] = __expf(l[c] - mx); ss += l[c]; }
        #pragma unroll
        for (int c = 0; c < 20; c++) out[row * 20 + c] = l[c] / ss;
    }
}

// ---------------- launcher ---------------------------------------------------
extern "C" void kernel_launch(void* const* d_in, const int* in_sizes, int n_in,
                              void* d_out, int out_size) {
    const int*   tokens = (const int*)d_in[0];
    const float* emb = (const float*)d_in[1];
    const float* Wx  = (const float*)d_in[2];
    const float* Wh  = (const float*)d_in[3];
    const float* b   = (const float*)d_in[4];
    const float* W1  = (const float*)d_in[5];
    const float* b1  = (const float*)d_in[6];
    const float* W2  = (const float*)d_in[7];
    const float* b2  = (const float*)d_in[8];
    const float* Wo  = (const float*)d_in[9];
    const float* bo  = (const float*)d_in[10];
    float* out = (float*)d_out;

    cudaFuncSetAttribute(k_phaseA, cudaFuncAttributeMaxDynamicSharedMemorySize, 159744);
    cudaFuncSetAttribute(k_recur, cudaFuncAttributeMaxDynamicSharedMemorySize, 104512);

    k_cvt_emb<<<(50000 * 38 + 255) / 256, 256>>>(emb);                          // 0
    k_cvt_rest<<<(987648 + 255) / 256, 256>>>(Wx, Wh, W1, W2, tokens);          // 1
    k_phaseA<<<dim3(16, 256), 256, 159744>>>(tokens, b);                        // 2
    k_recur<<<64, 256, 104512>>>();                                             // 3 <- profiled
    k_mlp<<<dim3(16, 4), 256>>>(0, b1);                                         // 4
    k_mlp<<<dim3(16, 4), 256>>>(1, b2);                                         // 5
    k_out<<<64, 128>>>(Wo, bo, out);                                            // 6
}

// round 6
// speedup vs baseline: 1.5051x; 1.5051x over previous
#include <cuda_runtime.h>
#include <cuda_bf16.h>
#include <stdint.h>

typedef __nv_bfloat16 bf16;

// ---------------- static device scratch (no runtime allocation) -------------
__device__ bf16 d_embB[(size_t)50000 * 304];   // padded bf16 embedding [v][304]
__device__ bf16 d_WxT[(size_t)2048 * 304];     // Wx transposed [n][304] bf16
__device__ bf16 d_WhB[512 * 2048];
__device__ bf16 d_W1B[512 * 1024];
__device__ bf16 d_W2B[1024 * 1024];
__device__ bf16 d_xg[(size_t)32768 * 2048];    // time-major [t][b][g]
__device__ bf16 d_h[2][64 * 512];              // ping-pong h
__device__ unsigned char d_maskT[512 * 64];    // [t][b]
__device__ bf16 d_a1[64 * 1024];
__device__ bf16 d_a2[64 * 1024];
__device__ unsigned int d_steps[512];          // per-step release flags
__device__ unsigned int d_bar;                 // arrival counter (monotonic)

// ---------------- helpers ---------------------------------------------------
__device__ __forceinline__ uint32_t pack_bf2(float a, float b) {
    __nv_bfloat162 t = __floats2bfloat162_rn(a, b);
    return *reinterpret_cast<uint32_t*>(&t);
}

__device__ __forceinline__ void mma16816(float* c, const uint32_t* a, const uint32_t* b) {
    asm volatile(
        "mma.sync.aligned.m16n8k16.row.col.f32.bf16.bf16.f32 "
        "{%0,%1,%2,%3},{%4,%5,%6,%7},{%8,%9},{%0,%1,%2,%3};"
        : "+f"(c[0]), "+f"(c[1]), "+f"(c[2]), "+f"(c[3])
        : "r"(a[0]), "r"(a[1]), "r"(a[2]), "r"(a[3]), "r"(b[0]), "r"(b[1]));
}

__device__ __forceinline__ void ldsm4(uint32_t* r, uint32_t addr) {
    asm volatile("ldmatrix.sync.aligned.m8n8.x4.shared.b16 {%0,%1,%2,%3}, [%4];"
                 : "=r"(r[0]), "=r"(r[1]), "=r"(r[2]), "=r"(r[3]) : "r"(addr));
}

__device__ __forceinline__ uint32_t s2u(const void* p) {
    return (uint32_t)__cvta_generic_to_shared(p);
}

__device__ __forceinline__ void cp16(uint32_t dst, const void* src) {
    asm volatile("cp.async.cg.shared.global [%0], [%1], 16;" :: "r"(dst), "l"(src));
}

__device__ __forceinline__ void cp_wait_all() {
    asm volatile("cp.async.commit_group;\ncp.async.wait_group 0;" ::: "memory");
}

__device__ __forceinline__ void st_release(unsigned int* p, unsigned int v) {
    asm volatile("st.global.release.gpu.b32 [%0], %1;" :: "l"(p), "r"(v) : "memory");
}

__device__ __forceinline__ unsigned int ld_acquire(const unsigned int* p) {
    unsigned int v;
    asm volatile("ld.global.acquire.gpu.b32 %0, [%1];" : "=r"(v) : "l"(p) : "memory");
    return v;
}

// ---------------- launch 0: vectorized embedding conversion ------------------
__global__ void k_cvt_emb(const float* __restrict__ e) {
    int i = blockIdx.x * 256 + threadIdx.x;
    if (i >= 50000 * 38) return;
    int row = i / 38, j = i - 38 * row;
    const float* src = e + (size_t)row * 300 + j * 8;
    float4 lo = *reinterpret_cast<const float4*>(src);
    float4 hi = make_float4(0.f, 0.f, 0.f, 0.f);
    if (j < 37) hi = *reinterpret_cast<const float4*>(src + 4);
    uint4 o;
    o.x = pack_bf2(lo.x, lo.y); o.y = pack_bf2(lo.z, lo.w);
    o.z = pack_bf2(hi.x, hi.y); o.w = pack_bf2(hi.z, hi.w);
    *reinterpret_cast<uint4*>(&d_embB[(size_t)row * 304 + j * 8]) = o;
}

// ---------------- launch 1: everything else (WxT, Wh/W1/W2, mask, zero) -----
__global__ void k_cvt_rest(const float* __restrict__ Wx, const float* __restrict__ Wh,
                           const float* __restrict__ W1, const float* __restrict__ W2,
                           const int* __restrict__ tokens) {
    int i = blockIdx.x * 256 + threadIdx.x;
    if (i < 622592) {                       // WxT (transpose, scalar)
        int n = i / 304, k = i - 304 * n;
        d_WxT[i] = __float2bfloat16(k < 300 ? Wx[(size_t)k * 2048 + n] : 0.f);
    } else if (i < 950272) {                // Wh/W1/W2, 8 elements per thread
        int j = i - 622592;
        const float* src; bf16* dst;
        if (j < 131072)      { src = Wh + (size_t)j * 8;            dst = d_WhB + (size_t)j * 8; }
        else if (j < 196608) { src = W1 + (size_t)(j - 131072) * 8; dst = d_W1B + (size_t)(j - 131072) * 8; }
        else                 { src = W2 + (size_t)(j - 196608) * 8; dst = d_W2B + (size_t)(j - 196608) * 8; }
        float4 lo = *reinterpret_cast<const float4*>(src);
        float4 hi = *reinterpret_cast<const float4*>(src + 4);
        uint4 o;
        o.x = pack_bf2(lo.x, lo.y); o.y = pack_bf2(lo.z, lo.w);
        o.z = pack_bf2(hi.x, hi.y); o.w = pack_bf2(hi.z, hi.w);
        *reinterpret_cast<uint4*>(dst) = o;
    } else if (i < 983040) {                // transposed mask
        int j = i - 950272;
        int t = j >> 6, b = j & 63;
        d_maskT[j] = (tokens[b * 512 + t] != 0) ? 1 : 0;
    } else if (i < 987136) {                // zero h[0]
        uint4 z = make_uint4(0u, 0u, 0u, 0u);
        reinterpret_cast<uint4*>(d_h[0])[i - 983040] = z;
    } else if (i < 987648) {                // zero step flags
        d_steps[i - 987136] = 0u;
    } else if (i == 987648) {               // zero arrival counter
        d_bar = 0u;
    }
}

// ---------------- launch 2: Phase A  xg = gather(emb)@Wx + b ----------------
__global__ void __launch_bounds__(256) k_phaseA(const int* __restrict__ tokens,
                                                const float* __restrict__ bias) {
    extern __shared__ bf16 smA[];
    bf16* As = smA;                 // 128 x 312
    bf16* Bs = smA + 128 * 312;     // 128 x 312
    __shared__ int stok[128];

    int tid = threadIdx.x;
    int n0 = blockIdx.x * 128;
    int m0 = blockIdx.y * 128;
    if (tid < 128) stok[tid] = tokens[m0 + tid];
    __syncthreads();

    {
        int row = tid >> 1, half = tid & 1;
        const bf16* sa = &d_embB[(size_t)stok[row] * 304 + half * 152];
        uint32_t da = s2u(&As[row * 312 + half * 152]);
        const bf16* sb = &d_WxT[(size_t)(n0 + row) * 304 + half * 152];
        uint32_t db = s2u(&Bs[row * 312 + half * 152]);
        #pragma unroll
        for (int j = 0; j < 19; j++) {
            cp16(da + j * 16, sa + j * 8);
            cp16(db + j * 16, sb + j * 8);
        }
        cp_wait_all();
    }
    __syncthreads();

    int w = tid >> 5, lane = tid & 31, g = lane >> 2, tq = lane & 3;
    int wm = (w >> 2) * 64;
    int wn = (w & 3) * 32;
    int lr = lane & 7, lm = lane >> 3;

    uint32_t aab[4], bab[2];
    #pragma unroll
    for (int mo = 0; mo < 4; mo++)
        aab[mo] = s2u(&As[(wm + mo * 16 + lr + (lm & 1) * 8) * 312 + (lm >> 1) * 8]);
    bab[0] = s2u(&Bs[(wn +      lr + (lm >> 1) * 8) * 312 + (lm & 1) * 8]);
    bab[1] = s2u(&Bs[(wn + 16 + lr + (lm >> 1) * 8) * 312 + (lm & 1) * 8]);

    float C[4][4][4];
    #pragma unroll
    for (int a = 0; a < 4; a++)
        #pragma unroll
        for (int b2 = 0; b2 < 4; b2++)
            #pragma unroll
            for (int c = 0; c < 4; c++) C[a][b2][c] = 0.f;

    #pragma unroll 1
    for (int ks = 0; ks < 19; ks++) {
        uint32_t B8[8];
        ldsm4(B8, bab[0] + ks * 32);
        ldsm4(B8 + 4, bab[1] + ks * 32);
        #pragma unroll
        for (int mo = 0; mo < 4; mo++) {
            uint32_t A4[4];
            ldsm4(A4, aab[mo] + ks * 32);
            mma16816(C[mo][0], A4, B8 + 0);
            mma16816(C[mo][1], A4, B8 + 2);
            mma16816(C[mo][2], A4, B8 + 4);
            mma16816(C[mo][3], A4, B8 + 6);
        }
    }

    #pragma unroll
    for (int mo = 0; mo < 4; mo++) {
        #pragma unroll
        for (int no = 0; no < 4; no++) {
            int gcol = n0 + wn + no * 8 + 2 * tq;
            float b0 = bias[gcol], b1v = bias[gcol + 1];
            int m1 = m0 + wm + mo * 16 + g;
            int m2 = m1 + 8;
            size_t o1 = ((size_t)((m1 & 511) * 64 + (m1 >> 9))) * 2048 + gcol;
            size_t o2 = ((size_t)((m2 & 511) * 64 + (m2 >> 9))) * 2048 + gcol;
            *reinterpret_cast<uint32_t*>(&d_xg[o1]) =
                pack_bf2(C[mo][no][0] + b0, C[mo][no][1] + b1v);
            *reinterpret_cast<uint32_t*>(&d_xg[o2]) =
                pack_bf2(C[mo][no][2] + b0, C[mo][no][3] + b1v);
        }
    }
}

// ---------------- launch 3 (profiled): recurrence ----------------------------
// 128 persistent CTAs x 4 units, 512 steps.  Per CTA/step:
//   g[64,16] = h[64,512] @ Ws[16,512]^T   (K split across 2 warp quads)
// dyn SMEM: Ws 16x520 bf16 (16640) | hs 64x520 bf16 (66560) |
//           gf 2x16x65 fp32 (8320) | ms 64  -> 91584 B
__global__ void __launch_bounds__(256, 1) k_recur() {
    extern __shared__ char sm[];
    bf16* Ws = reinterpret_cast<bf16*>(sm);
    bf16* hs = reinterpret_cast<bf16*>(sm + 16640);
    float* gf = reinterpret_cast<float*>(sm + 83200);
    uint32_t* ms4 = reinterpret_cast<uint32_t*>(sm + 91520);

    int tid = threadIdx.x, cta = blockIdx.x;
    int u0 = cta * 4;

    // Ws: 16 rows n (gate=n>>2, unit=u0+(n&3)) x K=512
    for (int i = tid; i < 16 * 512; i += 256) {
        int n = i & 15, k = i >> 4;
        Ws[n * 520 + k] = d_WhB[k * 2048 + (n >> 2) * 512 + u0 + (n & 3)];
    }

    int w = tid >> 5, lane = tid & 31, g = lane >> 2, tq = lane & 3;
    int mt = w & 3, kh = w >> 2;            // 4 m-tiles x 2 K-halves
    int lr = lane & 7, lm = lane >> 3;
    uint32_t a_base = s2u(&hs[(mt * 16 + lr + (lm & 1) * 8) * 520 + (lm >> 1) * 8 + kh * 256]);
    uint32_t b_base = s2u(&Ws[(lr + (lm >> 1) * 8) * 520 + (lm & 1) * 8 + kh * 256]);

    int eb = tid >> 2, eu = tid & 3;        // epilogue: batch eb, unit eu
    float cst = 0.f;
    __syncthreads();

    for (int t = 0; t < 512; t++) {
        // xg prefetch (consumed post-MMA)
        const bf16* xb = d_xg + (size_t)t * 131072 + eb * 2048 + u0 + eu;
        bf16 x0 = xb[0], x1 = xb[512], x2 = xb[1024], x3 = xb[1536];

        // stage h (64x512 bf16, 64KB) via uint4
        const bf16* hsrc = d_h[t & 1];
        #pragma unroll
        for (int j = 0; j < 16; j++) {
            int i = j * 256 + tid;
            int row = i >> 6, qc = i & 63;
            *reinterpret_cast<uint4*>(&hs[row * 520 + qc * 8]) =
                __ldcg(reinterpret_cast<const uint4*>(&hsrc[row * 512 + qc * 8]));
        }
        if (tid < 16)
            ms4[tid] = *reinterpret_cast<const uint32_t*>(&d_maskT[t * 64 + tid * 4]);
        __syncthreads();

        float C0[4] = {0.f, 0.f, 0.f, 0.f};
        float C1[4] = {0.f, 0.f, 0.f, 0.f};
        #pragma unroll 8
        for (int ks = 0; ks < 16; ks++) {
            uint32_t A4[4], B4[4];
            ldsm4(A4, a_base + ks * 32);
            ldsm4(B4, b_base + ks * 32);
            mma16816(C0, A4, B4);
            mma16816(C1, A4, B4 + 2);
        }
        {
            float* gfp = gf + kh * 16 * 65 + mt * 16 + g;
            gfp[(2 * tq) * 65]         = C0[0];
            gfp[(2 * tq + 1) * 65]     = C0[1];
            gfp[(2 * tq) * 65 + 8]     = C0[2];
            gfp[(2 * tq + 1) * 65 + 8] = C0[3];
            gfp[(8 + 2 * tq) * 65]         = C1[0];
            gfp[(8 + 2 * tq + 1) * 65]     = C1[1];
            gfp[(8 + 2 * tq) * 65 + 8]     = C1[2];
            gfp[(8 + 2 * tq + 1) * 65 + 8] = C1[3];
        }
        __syncthreads();

        // epilogue: thread = (batch eb, unit eu); sum the two K-halves
        bf16* hdst = d_h[(t + 1) & 1];
        {
            float gi = gf[eu * 65 + eb]        + gf[(16 + eu) * 65 + eb]      + __bfloat162float(x0);
            float gff = gf[(4 + eu) * 65 + eb]  + gf[(20 + eu) * 65 + eb]     + __bfloat162float(x1);
            float gc = gf[(8 + eu) * 65 + eb]  + gf[(24 + eu) * 65 + eb]      + __bfloat162float(x2);
            float go = gf[(12 + eu) * 65 + eb] + gf[(28 + eu) * 65 + eb]      + __bfloat162float(x3);
            float si = 1.f / (1.f + __expf(-gi));
            float sf = 1.f / (1.f + __expf(-gff));
            float so = 1.f / (1.f + __expf(-go));
            float cn = sf * cst + si * fmaxf(gc, 0.f);
            float hn = so * fmaxf(cn, 0.f);
            float hout;
            if ((ms4[eb >> 2] >> ((eb & 3) * 8)) & 0xff) { cst = cn; hout = hn; }
            else { hout = __bfloat162float(hs[eb * 520 + u0 + eu]); }
            hdst[eb * 512 + u0 + eu] = __float2bfloat16(hout);
        }
        __syncthreads();   // all h stores issued, hs/gf reusable

        if (t < 511) {
            // two-level barrier: atomic arrivals, single poller, broadcast flag
            if (tid == 0) {
                __threadfence();
                atomicAdd(&d_bar, 1u);
                if (cta == 0) {
                    unsigned tgt = 128u * (unsigned)(t + 1);
                    while (ld_acquire(&d_bar) < tgt) { }
                    st_release(&d_steps[t], 1u);
                } else {
                    while (ld_acquire(&d_steps[t]) == 0u) { }
                }
            }
            __syncthreads();
        }
    }
}

// ---------------- MLP layers -------------------------------------------------
__global__ void __launch_bounds__(256) k_mlp(int mode, const float* __restrict__ bias) {
    const bf16* A; const bf16* W; bf16* out; int K;
    if (mode == 0) { A = d_h[0]; W = d_W1B; out = d_a1; K = 512; }
    else           { A = d_a1;   W = d_W2B; out = d_a2; K = 1024; }
    int tid = threadIdx.x;
    int col = blockIdx.x * 64 + (tid & 63);
    int rb = blockIdx.y * 16 + (tid >> 6);
    float acc[4] = {0.f, 0.f, 0.f, 0.f};
    for (int k = 0; k < K; k++) {
        float wv = __bfloat162float(W[k * 1024 + col]);
        #pragma unroll
        for (int j = 0; j < 4; j++)
            acc[j] += __bfloat162float(A[(rb + 4 * j) * K + k]) * wv;
    }
    float bv = bias[col];
    #pragma unroll
    for (int j = 0; j < 4; j++)
        out[(rb + 4 * j) * 1024 + col] = __float2bfloat16(fmaxf(acc[j] + bv, 0.f));
}

// ---------------- logits + softmax ------------------------------------------
__global__ void __launch_bounds__(128) k_out(const float* __restrict__ Wo,
                                             const float* __restrict__ bo,
                                             float* __restrict__ out) {
    __shared__ float red[128 * 20];
    int row = blockIdx.x, tid = threadIdx.x;
    float p[20];
    #pragma unroll
    for (int c = 0; c < 20; c++) p[c] = 0.f;
    for (int k = tid; k < 1024; k += 128) {
        float a = __bfloat162float(d_a2[row * 1024 + k]);
        #pragma unroll
        for (int c = 0; c < 20; c++) p[c] += a * Wo[k * 20 + c];
    }
    #pragma unroll
    for (int c = 0; c < 20; c++) red[tid * 20 + c] = p[c];
    __syncthreads();
    for (int s = 64; s > 0; s >>= 1) {
        if (tid < s) {
            #pragma unroll
            for (int c = 0; c < 20; c++) red[tid * 20 + c] += red[(tid + s) * 20 + c];
        }
        __syncthreads();
    }
    if (tid == 0) {
        float l[20], mx = -1e30f, ss = 0.f;
        #pragma unroll
        for (int c = 0; c < 20; c++) { l[c] = red[c] + bo[c]; mx = fmaxf(mx, l[c]); }
        #pragma unroll
        for (int c = 0; c < 20; c++) { l[c] = __expf(l[c] - mx); ss += l[c]; }
        #pragma unroll
        for (int c = 0; c < 20; c++) out[row * 20 + c] = l[c] / ss;
    }
}

// ---------------- launcher ---------------------------------------------------
extern "C" void kernel_launch(void* const* d_in, const int* in_sizes, int n_in,
                              void* d_out, int out_size) {
    const int*   tokens = (const int*)d_in[0];
    const float* emb = (const float*)d_in[1];
    const float* Wx  = (const float*)d_in[2];
    const float* Wh  = (const float*)d_in[3];
    const float* b   = (const float*)d_in[4];
    const float* W1  = (const float*)d_in[5];
    const float* b1  = (const float*)d_in[6];
    const float* W2  = (const float*)d_in[7];
    const float* b2  = (const float*)d_in[8];
    const float* Wo  = (const float*)d_in[9];
    const float* bo  = (const float*)d_in[10];
    float* out = (float*)d_out;

    cudaFuncSetAttribute(k_phaseA, cudaFuncAttributeMaxDynamicSharedMemorySize, 159744);
    cudaFuncSetAttribute(k_recur, cudaFuncAttributeMaxDynamicSharedMemorySize, 91584);

    k_cvt_emb<<<(50000 * 38 + 255) / 256, 256>>>(emb);                          // 0
    k_cvt_rest<<<(987649 + 255) / 256, 256>>>(Wx, Wh, W1, W2, tokens);          // 1
    k_phaseA<<<dim3(16, 256), 256, 159744>>>(tokens, b);                        // 2
    k_recur<<<128, 256, 91584>>>();                                             // 3 <- profiled
    k_mlp<<<dim3(16, 4), 256>>>(0, b1);                                         // 4
    k_mlp<<<dim3(16, 4), 256>>>(1, b2);                                         // 5
    k_out<<<64, 128>>>(Wo, bo, out);                                            // 6
}